// round 17
// baseline (speedup 1.0000x reference)
#include <cuda_runtime.h>
#include <cuda_fp16.h>
#include <math.h>
#include <stdint.h>

#define BB 2
#define NN 8192
#define KK 32
#define CC 128
#define HH 128
#define ALPHA 0.3f
#define EPS 1e-6f

#define RT 64                    // rows per block tile
#define NT 256                   // threads per GEMM block (8 warps)
#define ASTH 136                 // A smem stride in halves (272B: cf for LDSM)
#define BSTH 136                 // B smem stride in halves
#define AS_HALVES (RT * ASTH)    // 8704
#define BS_HALVES (128 * BSTH)   // 17408
#define SMEM_BYTES ((AS_HALVES + BS_HALVES) * 2)   // 52224 B
#define VST 132                  // Vs float stride for epilogue

__device__ __half g_H[(size_t)BB * NN * HH];      // fp16 hidden, 4 MB
__device__ __half g_wsh[(size_t)BB * NN * HH];    // fp16 weighted-sum hidden, 4 MB
__device__ __half g_emb16[(size_t)BB * NN * CC];  // fp16 embeddings (from k1), 4 MB
__device__ __half g_Wh16[(CC + HH) * HH];         // fp16 Ww TRANSPOSED [n][k]

__device__ __forceinline__ void mma_f16(float c[4], uint32_t a0, uint32_t a1,
                                        uint32_t a2, uint32_t a3,
                                        uint32_t b0, uint32_t b1) {
    asm("mma.sync.aligned.m16n8k16.row.col.f32.f16.f16.f32 "
        "{%0,%1,%2,%3}, {%4,%5,%6,%7}, {%8,%9}, {%0,%1,%2,%3};"
        : "+f"(c[0]), "+f"(c[1]), "+f"(c[2]), "+f"(c[3])
        : "r"(a0), "r"(a1), "r"(a2), "r"(a3), "r"(b0), "r"(b1));
}
__device__ __forceinline__ void ldsm_x4(uint32_t& r0, uint32_t& r1,
                                        uint32_t& r2, uint32_t& r3,
                                        uint32_t addr) {
    asm volatile("ldmatrix.sync.aligned.m8n8.x4.shared.b16 {%0,%1,%2,%3}, [%4];"
                 : "=r"(r0), "=r"(r1), "=r"(r2), "=r"(r3) : "r"(addr));
}
__device__ __forceinline__ uint32_t smem_u32(const void* p) {
    uint32_t r;
    asm("{ .reg .u64 t; cvta.to.shared.u64 t, %1; cvt.u32.u64 %0, t; }"
        : "=r"(r) : "l"(p));
    return r;
}
__device__ __forceinline__ float leaky(float v) {
    return (v >= 0.f) ? v : ALPHA * v;
}
__device__ __forceinline__ uint32_t h2_u32(float lo, float hi) {
    __half2 h = __floats2half2_rn(lo, hi);
    return *(uint32_t*)&h;
}

// ---- stage A from fp32, also export fp16 copy to global --------------------
__device__ __forceinline__ void stage_A_f32_exp(__half* __restrict__ As,
                                                const float* __restrict__ src,
                                                __half* __restrict__ gdst, int t) {
    const float4* s4 = (const float4*)src;
#pragma unroll
    for (int i = 0; i < (RT * CC / 4) / NT; i++) {   // 8 iters
        int id = t + i * NT;
        int row = id >> 5;
        int c = (id & 31) << 2;
        float4 v = s4[id];
        uint2 u = make_uint2(h2_u32(v.x, v.y), h2_u32(v.z, v.w));
        *(uint2*)&As[row * ASTH + c] = u;
        *(uint2*)&gdst[id * 4] = u;    // contiguous [row][c] fp16, coalesced
    }
}
// ---- stage A: RT rows x 128 halves raw copy ---------------------------------
__device__ __forceinline__ void stage_A_h16(__half* __restrict__ As,
                                            const __half* __restrict__ src, int t) {
    const uint4* s4 = (const uint4*)src;   // 8 halves each
#pragma unroll
    for (int i = 0; i < (RT * CC / 8) / NT; i++) {   // 4 iters
        int id = t + i * NT;
        int row = id >> 4;
        int c8 = (id & 15) << 3;
        *(uint4*)&As[row * ASTH + c8] = s4[id];
    }
}
// ---- stage B transposed from fp32 W[k][n] -> Bt[n][k] fp16 ------------------
__device__ __forceinline__ void stage_BT_cvt(__half* __restrict__ Bs,
                                             const float* __restrict__ W, int t) {
#pragma unroll
    for (int it = 0; it < 4; it++) {
        int id = t + it * NT;
        int k0 = (id >> 5) * 4;
        int h0 = (id & 31) * 4;
        float4 r0 = *(const float4*)(W + (k0 + 0) * HH + h0);
        float4 r1 = *(const float4*)(W + (k0 + 1) * HH + h0);
        float4 r2 = *(const float4*)(W + (k0 + 2) * HH + h0);
        float4 r3 = *(const float4*)(W + (k0 + 3) * HH + h0);
        *(uint2*)&Bs[(h0 + 0) * BSTH + k0] = make_uint2(h2_u32(r0.x, r1.x), h2_u32(r2.x, r3.x));
        *(uint2*)&Bs[(h0 + 1) * BSTH + k0] = make_uint2(h2_u32(r0.y, r1.y), h2_u32(r2.y, r3.y));
        *(uint2*)&Bs[(h0 + 2) * BSTH + k0] = make_uint2(h2_u32(r0.z, r1.z), h2_u32(r2.z, r3.z));
        *(uint2*)&Bs[(h0 + 3) * BSTH + k0] = make_uint2(h2_u32(r0.w, r1.w), h2_u32(r2.w, r3.w));
    }
}
// ---- stage B raw copy from pre-transposed g_Wh16 [n][256k] ------------------
__device__ __forceinline__ void stage_B_copy(__half* __restrict__ Bs,
                                             const __half* __restrict__ Wt,
                                             int koff, int t) {
#pragma unroll
    for (int i = 0; i < (128 * 128 / 8) / NT; i++) {  // 8 iters
        int id = t + i * NT;
        int row = id >> 4;
        int c8 = (id & 15) << 3;
        *(uint4*)&Bs[row * BSTH + c8] =
            *(const uint4*)&Wt[row * 256 + koff + c8];
    }
}

// ---- fp16 tensor-core mainloop over K=128, ldmatrix fragment loads ---------
// 8 warps: warp w owns cols n0=w*16 (2 n-tiles), all 64 rows (4 m-tiles).
// Per k-step: 1 LDSM.x4 (B, both n-tiles) + 4 LDSM.x4 (A) + 8 MMA.
__device__ __forceinline__ void gemm16(const __half* __restrict__ As,
                                       const __half* __restrict__ Bs,
                                       int lane, int n0, float c[4][2][4]) {
    const int r8 = lane & 7;
    const int s1 = (lane >> 3) & 1;
    const int s2 = (lane >> 4) & 1;
    const uint32_t a_base = smem_u32(As) +
        (uint32_t)(((r8 + s1 * 8) * ASTH + s2 * 8) * 2);
    const uint32_t b_base = smem_u32(Bs) +
        (uint32_t)(((n0 + r8 + s2 * 8) * BSTH + s1 * 8) * 2);
#pragma unroll
    for (int ks = 0; ks < 8; ks++) {
        uint32_t b0, b1, b2, b3;
        ldsm_x4(b0, b1, b2, b3, b_base + ks * 32);
#pragma unroll
        for (int mt = 0; mt < 4; mt++) {
            uint32_t a0, a1, a2, a3;
            ldsm_x4(a0, a1, a2, a3, a_base + mt * 16 * ASTH * 2 + ks * 32);
            mma_f16(c[mt][0], a0, a1, a2, a3, b0, b1);
            mma_f16(c[mt][1], a0, a1, a2, a3, b2, b3);
        }
    }
}

// ---------------------------------------------------------------------------
// K1: H = leaky(emb @ Qw + Qb) -> fp16; exports emb16; pre-converts Ww^T.
// ---------------------------------------------------------------------------
__global__ void __launch_bounds__(NT) k1_qgemm(const float* __restrict__ emb,
                                               const float* __restrict__ Qw,
                                               const float* __restrict__ Qb,
                                               const float* __restrict__ Ww) {
    extern __shared__ __half smh[];
    __half* As = smh;
    __half* Bs = smh + AS_HALVES;
    const int t = threadIdx.x;
    const int lane = t & 31;
    const int n0 = (t >> 5) * 16;
    const int row0 = blockIdx.x * RT;

    // cooperative Ww -> g_Wh16 transposed [n][k]
    {
        const int id = blockIdx.x * NT + t;
        if (id < (CC + HH) * HH) {
            int n = id >> 8;          // 0..127
            int k = id & 255;         // 0..255
            g_Wh16[id] = __float2half(Ww[k * HH + n]);
        }
    }

    stage_A_f32_exp(As, emb + (size_t)row0 * CC, g_emb16 + (size_t)row0 * CC, t);
    stage_BT_cvt(Bs, Qw, t);
    __syncthreads();

    float c[4][2][4];
#pragma unroll
    for (int mt = 0; mt < 4; mt++)
#pragma unroll
        for (int nt = 0; nt < 2; nt++)
#pragma unroll
            for (int i = 0; i < 4; i++) c[mt][nt][i] = 0.f;

    gemm16(As, Bs, lane, n0, c);

#pragma unroll
    for (int nt = 0; nt < 2; nt++) {
        const int col = n0 + nt * 8 + 2 * (lane & 3);
        const float2 bias = *(const float2*)(Qb + col);
#pragma unroll
        for (int mt = 0; mt < 4; mt++) {
            const int r0 = row0 + mt * 16 + (lane >> 2);
            __half2 v0 = __floats2half2_rn(leaky(c[mt][nt][0] + bias.x),
                                           leaky(c[mt][nt][1] + bias.y));
            __half2 v1 = __floats2half2_rn(leaky(c[mt][nt][2] + bias.x),
                                           leaky(c[mt][nt][3] + bias.y));
            *(__half2*)&g_H[(size_t)r0 * HH + col] = v0;
            *(__half2*)&g_H[(size_t)(r0 + 8) * HH + col] = v1;
        }
    }
}

// ---------------------------------------------------------------------------
// K2: wsh[b,n,h] = sum_k H[b,js[k],h]*ws[k] / (sum_k ws + eps) -> fp16
// ---------------------------------------------------------------------------
__global__ void __launch_bounds__(128) k2_gather(const float* __restrict__ weights,
                                                 const int* __restrict__ ns) {
    const int n = blockIdx.x;
    const int t = threadIdx.x;
    const int c4 = t & 31;
    const int kg = t >> 5;

    __shared__ float ws[KK];
    __shared__ int   js[KK];
    __shared__ float wsum_s;
    __shared__ float4 red0[4][32];
    __shared__ float4 red1[4][32];

    if (t < KK) {
        int j = ns[n * KK + t];
        js[t] = j;
        float w = weights[(size_t)n * NN + j];
        ws[t] = w;
#pragma unroll
        for (int off = 16; off; off >>= 1)
            w += __shfl_xor_sync(0xffffffffu, w, off);
        if (t == 0) wsum_s = w;
    }
    __syncthreads();

    const __half* H0 = g_H;
    const __half* H1 = g_H + (size_t)NN * HH;
    float4 a0 = make_float4(0.f, 0.f, 0.f, 0.f);
    float4 a1 = make_float4(0.f, 0.f, 0.f, 0.f);
#pragma unroll
    for (int k = kg; k < KK; k += 4) {
        const int j = js[k];
        const float w = ws[k];
        const __half2* p0 = (const __half2*)(H0 + (size_t)j * HH + 4 * c4);
        const __half2* p1 = (const __half2*)(H1 + (size_t)j * HH + 4 * c4);
        float2 x0 = __half22float2(p0[0]);
        float2 y0 = __half22float2(p0[1]);
        float2 x1 = __half22float2(p1[0]);
        float2 y1 = __half22float2(p1[1]);
        a0.x = fmaf(x0.x, w, a0.x); a0.y = fmaf(x0.y, w, a0.y);
        a0.z = fmaf(y0.x, w, a0.z); a0.w = fmaf(y0.y, w, a0.w);
        a1.x = fmaf(x1.x, w, a1.x); a1.y = fmaf(x1.y, w, a1.y);
        a1.z = fmaf(y1.x, w, a1.z); a1.w = fmaf(y1.y, w, a1.w);
    }
    red0[kg][c4] = a0;
    red1[kg][c4] = a1;
    __syncthreads();

    if (t < 64) {
        const int b = t >> 5;
        const int c = t & 31;
        const float4 p0 = b ? red1[0][c] : red0[0][c];
        const float4 p1 = b ? red1[1][c] : red0[1][c];
        const float4 p2 = b ? red1[2][c] : red0[2][c];
        const float4 p3 = b ? red1[3][c] : red0[3][c];
        const float inv = 1.f / (wsum_s + EPS);
        uint2 o = make_uint2(
            h2_u32((p0.x + p1.x + p2.x + p3.x) * inv,
                   (p0.y + p1.y + p2.y + p3.y) * inv),
            h2_u32((p0.z + p1.z + p2.z + p3.z) * inv,
                   (p0.w + p1.w + p2.w + p3.w) * inv));
        *(uint2*)&g_wsh[((size_t)b * NN + n) * HH + 4 * c] = o;
    }
}

// ---------------------------------------------------------------------------
// K3: out = normalize(leaky([emb | wsh] @ Ww + Wb)), two fp16 K=128 stages.
// Stage-0 A is raw fp16 copy (g_emb16); stage-1 operands register-prefetched
// before gemm0 so their LDG latency hides under the first gemm.
// ---------------------------------------------------------------------------
__global__ void __launch_bounds__(NT) k3_out(const float* __restrict__ Wb,
                                             float* __restrict__ out) {
    extern __shared__ __half smh[];
    __half* As = smh;
    __half* Bs = smh + AS_HALVES;
    const int t = threadIdx.x;
    const int lane = t & 31;
    const int n0 = (t >> 5) * 16;
    const int row0 = blockIdx.x * RT;

    float c[4][2][4];
#pragma unroll
    for (int mt = 0; mt < 4; mt++)
#pragma unroll
        for (int nt = 0; nt < 2; nt++)
#pragma unroll
            for (int i = 0; i < 4; i++) c[mt][nt][i] = 0.f;

    // stage 0: A = emb16 raw copy, B = Ww_top raw copy
    stage_A_h16(As, g_emb16 + (size_t)row0 * CC, t);
    stage_B_copy(Bs, g_Wh16, 0, t);

    // prefetch stage-1 operands into registers (LDG overlaps gemm0)
    uint4 pw[4], pb[8];
    {
        const uint4* s4 = (const uint4*)(g_wsh + (size_t)row0 * HH);
#pragma unroll
        for (int i = 0; i < 4; i++) pw[i] = s4[t + i * NT];
#pragma unroll
        for (int i = 0; i < 8; i++) {
            int id = t + i * NT;
            int row = id >> 4;
            int c8 = (id & 15) << 3;
            pb[i] = *(const uint4*)&g_Wh16[row * 256 + 128 + c8];
        }
    }
    __syncthreads();
    gemm16(As, Bs, lane, n0, c);
    __syncthreads();

    // stage 1 from registers: A = wsh, B = Ww_bot
#pragma unroll
    for (int i = 0; i < 4; i++) {
        int id = t + i * NT;
        *(uint4*)&As[(id >> 4) * ASTH + ((id & 15) << 3)] = pw[i];
    }
#pragma unroll
    for (int i = 0; i < 8; i++) {
        int id = t + i * NT;
        *(uint4*)&Bs[(id >> 4) * BSTH + ((id & 15) << 3)] = pb[i];
    }
    __syncthreads();
    gemm16(As, Bs, lane, n0, c);
    __syncthreads();   // all reads of As/Bs done before reuse as Vs

    // epilogue: bias + leaky into Vs (fp32), row-norm, store
    float* Vs = (float*)smh;   // 64 x VST floats = 33792 B, fits
#pragma unroll
    for (int nt = 0; nt < 2; nt++) {
        const int col = n0 + nt * 8 + 2 * (lane & 3);
        const float2 bias = *(const float2*)(Wb + col);
#pragma unroll
        for (int mt = 0; mt < 4; mt++) {
            const int r = mt * 16 + (lane >> 2);
            *(float2*)&Vs[r * VST + col] =
                make_float2(leaky(c[mt][nt][0] + bias.x),
                            leaky(c[mt][nt][1] + bias.y));
            *(float2*)&Vs[(r + 8) * VST + col] =
                make_float2(leaky(c[mt][nt][2] + bias.x),
                            leaky(c[mt][nt][3] + bias.y));
        }
    }
    __syncthreads();

    // 4 threads per row, 32 cols each
    const int row = t >> 2;
    const int q = t & 3;
    float4 vv[8];
    float ssq = 0.f;
#pragma unroll
    for (int i = 0; i < 8; i++) {
        vv[i] = *(const float4*)&Vs[row * VST + q * 32 + i * 4];
        ssq = fmaf(vv[i].x, vv[i].x, ssq);
        ssq = fmaf(vv[i].y, vv[i].y, ssq);
        ssq = fmaf(vv[i].z, vv[i].z, ssq);
        ssq = fmaf(vv[i].w, vv[i].w, ssq);
    }
    ssq += __shfl_xor_sync(0xffffffffu, ssq, 1);
    ssq += __shfl_xor_sync(0xffffffffu, ssq, 2);
    const float inv = 1.f / (sqrtf(ssq) + EPS);
    float* o = out + (size_t)(row0 + row) * HH + q * 32;
#pragma unroll
    for (int i = 0; i < 8; i++) {
        *(float4*)(o + i * 4) = make_float4(vv[i].x * inv, vv[i].y * inv,
                                            vv[i].z * inv, vv[i].w * inv);
    }
}

// ---------------------------------------------------------------------------
extern "C" void kernel_launch(void* const* d_in, const int* in_sizes, int n_in,
                              void* d_out, int out_size) {
    const float* emb     = (const float*)d_in[0];  // (B, N, C)
    const float* weights = (const float*)d_in[1];  // (N, N)
    const int*   ns      = (const int*)  d_in[2];  // (N, K)
    const float* Qw      = (const float*)d_in[3];  // (C, H)
    const float* Qb      = (const float*)d_in[4];  // (H,)
    const float* Ww      = (const float*)d_in[5];  // (C+H, H)
    const float* Wb      = (const float*)d_in[6];  // (H,)
    float* out = (float*)d_out;                    // (B, N, H)

    (void)in_sizes; (void)n_in; (void)out_size;

    cudaFuncSetAttribute(k1_qgemm, cudaFuncAttributeMaxDynamicSharedMemorySize,
                         SMEM_BYTES);
    cudaFuncSetAttribute(k3_out, cudaFuncAttributeMaxDynamicSharedMemorySize,
                         SMEM_BYTES);

    k1_qgemm<<<(BB * NN) / RT, NT, SMEM_BYTES>>>(emb, Qw, Qb, Ww);
    k2_gather<<<NN, 128>>>(weights, ns);
    k3_out<<<(BB * NN) / RT, NT, SMEM_BYTES>>>(Wb, out);
}